// round 14
// baseline (speedup 1.0000x reference)
#include <cuda_runtime.h>
#include <cstdio>

#define Bb 64
#define Pp 10000
#define Ee 128
#define Cc 100
#define CAP 384
#define BC (Bb*Cc)

// ---------------- scratch (no allocations allowed) ----------------
__device__ int   g_cnt[BC];
__device__ int   g_idx[BC*CAP];
__device__ float g_means[BC*Ee];
__device__ float g_wt[Ee*Ee];        // W transposed: g_wt[k*Ee+e] = W[e*Ee+k]
__device__ int   g_ids[Bb*Pp];
__device__ int   g_is64;

__device__ __forceinline__ void f4add(float4& a, const float4 b) {
    a.x += b.x; a.y += b.y; a.z += b.z; a.w += b.w;
}

// ---------------- K0: zero counters + W transpose + dtype detect ----------------
__global__ void k_init(const int* __restrict__ ids32, const float* __restrict__ W) {
    int i = blockIdx.x * blockDim.x + threadIdx.x;
    if (i < BC) g_cnt[i] = 0;
    if (i < Ee*Ee) {                      // one-time scattered transpose (tiny)
        int k = i >> 7, e = i & 127;
        g_wt[i] = W[e*Ee + k];
    }
    if (i == 0) {
        int all0 = 1;
        #pragma unroll 4
        for (int j = 0; j < 64; j++) {
            if (ids32[2*j + 1] != 0) { all0 = 0; break; }
        }
        g_is64 = all0;
    }
}

// ---------------- K1: bucket node indices by (batch, cluster) ----------------
__global__ void k_bucket(const void* __restrict__ ids_raw) {
    int i = blockIdx.x * blockDim.x + threadIdx.x;   // over B*P
    if (i >= Bb*Pp) return;
    int c;
    if (g_is64) c = (int)((const long long*)ids_raw)[i];
    else        c = ((const int*)ids_raw)[i];
    g_ids[i] = c;
    int b = i / Pp;
    int pos = atomicAdd(&g_cnt[b*Cc + c], 1);
    if (pos < CAP) g_idx[(b*Cc + c)*CAP + pos] = i - b*Pp;
}

// ---------------- K2: segment mean (float4 rows, warp-per-row, MLP=8) ----------------
__global__ void __launch_bounds__(128) k_mean(const float* __restrict__ enc) {
    int bc   = blockIdx.x;            // (b, c)
    int b    = bc / Cc;
    int warp = threadIdx.x >> 5;
    int lane = threadIdx.x & 31;

    __shared__ int    s_idx[CAP];
    __shared__ float4 s_red[3][32];

    int n_full = g_cnt[bc];
    int n = n_full < CAP ? n_full : CAP;
    for (int i = threadIdx.x; i < n; i += 128) s_idx[i] = g_idx[bc*CAP + i];
    __syncthreads();

    const float4* __restrict__ base4 = (const float4*)(enc + (size_t)b * Pp * Ee);
    float4 a0 = {0,0,0,0}, a1 = a0, a2 = a0, a3 = a0;

    int i = warp;
    // 8 loads in flight per warp (MLP=8) against 577-cyc DRAM latency
    for (; i + 28 < n; i += 32) {
        float4 v0 = __ldcs(&base4[(size_t)s_idx[i     ]*32 + lane]);
        float4 v1 = __ldcs(&base4[(size_t)s_idx[i +  4]*32 + lane]);
        float4 v2 = __ldcs(&base4[(size_t)s_idx[i +  8]*32 + lane]);
        float4 v3 = __ldcs(&base4[(size_t)s_idx[i + 12]*32 + lane]);
        float4 v4 = __ldcs(&base4[(size_t)s_idx[i + 16]*32 + lane]);
        float4 v5 = __ldcs(&base4[(size_t)s_idx[i + 20]*32 + lane]);
        float4 v6 = __ldcs(&base4[(size_t)s_idx[i + 24]*32 + lane]);
        float4 v7 = __ldcs(&base4[(size_t)s_idx[i + 28]*32 + lane]);
        f4add(a0, v0); f4add(a1, v1); f4add(a2, v2); f4add(a3, v3);
        f4add(a0, v4); f4add(a1, v5); f4add(a2, v6); f4add(a3, v7);
    }
    for (; i + 12 < n; i += 16) {
        float4 v0 = __ldcs(&base4[(size_t)s_idx[i     ]*32 + lane]);
        float4 v1 = __ldcs(&base4[(size_t)s_idx[i +  4]*32 + lane]);
        float4 v2 = __ldcs(&base4[(size_t)s_idx[i +  8]*32 + lane]);
        float4 v3 = __ldcs(&base4[(size_t)s_idx[i + 12]*32 + lane]);
        f4add(a0, v0); f4add(a1, v1); f4add(a2, v2); f4add(a3, v3);
    }
    for (; i < n; i += 4)
        f4add(a0, __ldcs(&base4[(size_t)s_idx[i]*32 + lane]));

    f4add(a0, a1); f4add(a2, a3); f4add(a0, a2);

    if (warp) s_red[warp-1][lane] = a0;
    __syncthreads();
    if (warp == 0) {
        f4add(a0, s_red[0][lane]);
        f4add(a0, s_red[1][lane]);
        f4add(a0, s_red[2][lane]);
        float inv = 1.f / (float)(n_full > 0 ? n_full : 1);
        a0.x *= inv; a0.y *= inv; a0.z *= inv; a0.w *= inv;
        ((float4*)g_means)[(size_t)bc*32 + lane] = a0;
    }
}

// ---------------- K3: projection GEMM  out = means @ W^T + b ----------------
// v7: K-split=2 + EXPLICIT DOUBLE BUFFER. launch_bounds(256,2) raises the reg
// budget to 128 so the prefetched m/w buffers (extra 32 regs) fit; the 8
// LDS.128 of step k+1 issue while the 64 FFMA of step k drain, hiding the
// 29-cyc LDS latency (regs=71 at (256,3) forbade this -> issue stalled at 31%).
#define PROJ_SMEM ((16*Ee + Ee*Ee) * 4)          // 8KB + 64KB = 72KB
__global__ void __launch_bounds__(256, 2) k_proj(const float* __restrict__ bias,
                                                 float* __restrict__ ce) {
    extern __shared__ float smem[];
    float* sM = smem;                  // [16][Ee]
    float* sW = smem + 16*Ee;          // [Ee][Ee] k-major, unpadded

    int tid = threadIdx.x;
    int row_base = blockIdx.x * 16;

    // stage 16 mean rows (float4, coalesced)
    const float4* gm4 = (const float4*)(g_means + (size_t)row_base*Ee);
    float4* sM4 = (float4*)sM;
    for (int j = tid; j < 16*Ee/4; j += 256) sM4[j] = gm4[j];

    // stage Wt: straight float4 copy (coalesced LDG.128 / conflict-free STS.128)
    const float4* wt4 = (const float4*)g_wt;
    float4* sW4 = (float4*)sW;
    for (int j = tid; j < Ee*Ee/4; j += 256) sW4[j] = wt4[j];
    __syncthreads();

    int half = tid >> 7;               // k-half: 0 or 1
    int t    = tid & 127;
    int cg   = t & 31;                 // cols 4*cg .. 4*cg+3
    int rg   = t >> 5;                 // rows 4*rg .. 4*rg+3
    int kbase = half * 16;             // in k4 units

    float4 acc[4] = {{0,0,0,0},{0,0,0,0},{0,0,0,0},{0,0,0,0}};
    float4 mA[4], wA[4], mB[4], wB[4];

    // prefetch k4 = 0
    #pragma unroll
    for (int r = 0; r < 4; r++) mA[r] = sM4[(rg*4 + r)*32 + kbase];
    #pragma unroll
    for (int j = 0; j < 4; j++) wA[j] = sW4[(kbase*4 + j)*32 + cg];

    #pragma unroll
    for (int k4 = 0; k4 < 16; k4++) {
        float4 *m = (k4 & 1) ? mB : mA;
        float4 *w = (k4 & 1) ? wB : wA;
        float4 *mn = (k4 & 1) ? mA : mB;
        float4 *wn = (k4 & 1) ? wA : wB;
        if (k4 < 15) {                 // prefetch next step into the other buffer
            #pragma unroll
            for (int r = 0; r < 4; r++) mn[r] = sM4[(rg*4 + r)*32 + kbase + k4 + 1];
            #pragma unroll
            for (int j = 0; j < 4; j++) wn[j] = sW4[((kbase + k4 + 1)*4 + j)*32 + cg];
        }
        #pragma unroll
        for (int r = 0; r < 4; r++) {
            acc[r].x += m[r].x*w[0].x + m[r].y*w[1].x + m[r].z*w[2].x + m[r].w*w[3].x;
            acc[r].y += m[r].x*w[0].y + m[r].y*w[1].y + m[r].z*w[2].y + m[r].w*w[3].y;
            acc[r].z += m[r].x*w[0].z + m[r].y*w[1].z + m[r].z*w[2].z + m[r].w*w[3].z;
            acc[r].w += m[r].x*w[0].w + m[r].y*w[1].w + m[r].z*w[2].w + m[r].w*w[3].w;
        }
    }

    // combine the two k-halves through smem (reuse sW; pad-5 => conflict-free)
    __syncthreads();
    float4* sR = (float4*)sW;          // [128][5] float4 (10KB of sW)
    if (half == 1) {
        #pragma unroll
        for (int r = 0; r < 4; r++) sR[t*5 + r] = acc[r];
    }
    __syncthreads();
    if (half == 0) {
        float4 bb = ((const float4*)bias)[cg];
        #pragma unroll
        for (int r = 0; r < 4; r++) {
            f4add(acc[r], sR[t*5 + r]);
            f4add(acc[r], bb);
            ((float4*)(ce + (size_t)(row_base + rg*4 + r)*Ee))[cg] = acc[r];
        }
    }
}

// ---------------- K4: gather projected cluster embs back to nodes ----------------
// PCH=1250: 8 blocks/batch (was 16) halves the table re-staging L2 traffic.
#define PCH 1250
#define GATHER_SMEM ((Cc*Ee + PCH + 3) * 4)      // 51.2KB + 5KB
__global__ void __launch_bounds__(256) k_gather(const float* __restrict__ ce,
                                                float* __restrict__ gn) {
    extern __shared__ float s_dyn[];
    float* s_tab = s_dyn;                       // [Cc][Ee]
    int*   s_id  = (int*)(s_dyn + Cc*Ee);       // [PCH]

    int b  = blockIdx.y;
    int p0 = blockIdx.x * PCH;
    int cnt = Pp - p0; if (cnt > PCH) cnt = PCH;

    const float4* __restrict__ cb4 = (const float4*)(ce + (size_t)b * Cc * Ee);
    for (int j = threadIdx.x; j < Cc*Ee/4; j += 256)
        ((float4*)s_tab)[j] = cb4[j];
    const int* __restrict__ idb = g_ids + b*Pp + p0;
    for (int j = threadIdx.x; j < cnt; j += 256)
        s_id[j] = idb[j];
    __syncthreads();

    int lane = threadIdx.x & 31;
    int warp = threadIdx.x >> 5;
    float4* __restrict__ out = (float4*)(gn + ((size_t)b*Pp + p0)*Ee);

    int p = warp;
    for (; p + 8 < cnt; p += 16) {
        int c0 = s_id[p], c1 = s_id[p + 8];
        float4 v0 = ((const float4*)(s_tab + c0*Ee))[lane];
        float4 v1 = ((const float4*)(s_tab + c1*Ee))[lane];
        __stcs(&out[(size_t)p      *32 + lane], v0);
        __stcs(&out[(size_t)(p + 8)*32 + lane], v1);
    }
    for (; p < cnt; p += 8) {
        int c = s_id[p];
        float4 v = ((const float4*)(s_tab + c*Ee))[lane];
        __stcs(&out[(size_t)p*32 + lane], v);
    }
}

// ---------------- launch ----------------
extern "C" void kernel_launch(void* const* d_in, const int* in_sizes, int n_in,
                              void* d_out, int out_size) {
    const float* enc  = nullptr;
    const void*  ids  = nullptr;
    const float* W    = nullptr;
    const float* bias = nullptr;
    for (int i = 0; i < n_in; i++) {
        switch (in_sizes[i]) {
            case Bb*Pp*Ee: enc  = (const float*)d_in[i]; break;
            case Bb*Pp:    ids  = d_in[i];               break;
            case Ee*Ee:    W    = (const float*)d_in[i]; break;
            case Ee:       bias = (const float*)d_in[i]; break;
            default: break;
        }
    }

    float* ce = (float*)d_out;                       // [B, C, E]
    float* gn = (float*)d_out + (size_t)BC * Ee;     // [B, P, E]

    cudaFuncSetAttribute(k_proj,   cudaFuncAttributeMaxDynamicSharedMemorySize, PROJ_SMEM);
    cudaFuncSetAttribute(k_gather, cudaFuncAttributeMaxDynamicSharedMemorySize, GATHER_SMEM);

    k_init  <<<(Ee*Ee + 255)/256, 256>>>((const int*)ids, W);
    k_bucket<<<(Bb*Pp + 255)/256, 256>>>(ids);
    k_mean  <<<BC, 128>>>(enc);
    k_proj  <<<BC/16, 256, PROJ_SMEM>>>(bias, ce);
    k_gather<<<dim3((Pp + PCH - 1)/PCH, Bb), 256, GATHER_SMEM>>>(ce, gn);
}

// round 15
// speedup vs baseline: 1.0311x; 1.0311x over previous
#include <cuda_runtime.h>
#include <cstdio>

#define Bb 64
#define Pp 10000
#define Ee 128
#define Cc 100
#define CAP 384
#define BC (Bb*Cc)

// ---------------- scratch (no allocations allowed) ----------------
__device__ int   g_cnt[BC];
__device__ int   g_idx[BC*CAP];
__device__ float g_wt[Ee*Ee];        // W transposed: g_wt[k*Ee+e] = W[e*Ee+k]
__device__ int   g_ids[Bb*Pp];
__device__ int   g_is64;

__device__ __forceinline__ void f4add(float4& a, const float4 b) {
    a.x += b.x; a.y += b.y; a.z += b.z; a.w += b.w;
}

// ---------------- K0: zero counters + W transpose + dtype detect ----------------
__global__ void k_init(const int* __restrict__ ids32, const float* __restrict__ W) {
    int i = blockIdx.x * blockDim.x + threadIdx.x;
    if (i < BC) g_cnt[i] = 0;
    if (i < Ee*Ee) {                      // one-time scattered transpose (tiny)
        int k = i >> 7, e = i & 127;
        g_wt[i] = W[e*Ee + k];
    }
    if (i == 0) {
        int all0 = 1;
        #pragma unroll 4
        for (int j = 0; j < 64; j++) {
            if (ids32[2*j + 1] != 0) { all0 = 0; break; }
        }
        g_is64 = all0;
    }
}

// ---------------- K1: bucket node indices by (batch, cluster) ----------------
__global__ void k_bucket(const void* __restrict__ ids_raw) {
    int i = blockIdx.x * blockDim.x + threadIdx.x;   // over B*P
    if (i >= Bb*Pp) return;
    int c;
    if (g_is64) c = (int)((const long long*)ids_raw)[i];
    else        c = ((const int*)ids_raw)[i];
    g_ids[i] = c;
    int b = i / Pp;
    int pos = atomicAdd(&g_cnt[b*Cc + c], 1);
    if (pos < CAP) g_idx[(b*Cc + c)*CAP + pos] = i - b*Pp;
}

// ---------------- K2: fused segment-mean + projection ----------------
// Mean phase: float4 rows, warp-per-row, MLP=8 (DRAM-bound, ~55us chip-wide).
// Proj phase (NEW): ce[bc] depends only on this block's mean row, so each of
// the 128 threads computes one output column: acc = bias[t] + sum_k mean[k] *
// Wt[k][t]. Wt reads are 128B/warp coalesced LDGs that hit L1 after the first
// block on each SM (Wt=64KB fits L1D; enc streams use __ldcs = evict-first).
// The tail's LSU/L1 work hides under the mean phase's DRAM latency -> the old
// 17.8us k_proj kernel is deleted outright.
__global__ void __launch_bounds__(128) k_mean(const float* __restrict__ enc,
                                              const float* __restrict__ bias,
                                              float* __restrict__ ce) {
    int bc   = blockIdx.x;            // (b, c)
    int b    = bc / Cc;
    int warp = threadIdx.x >> 5;
    int lane = threadIdx.x & 31;
    int t    = threadIdx.x;

    __shared__ int    s_idx[CAP];
    __shared__ float4 s_red[3][32];
    __shared__ float  s_mean[Ee];

    int n_full = g_cnt[bc];
    int n = n_full < CAP ? n_full : CAP;
    for (int i = t; i < n; i += 128) s_idx[i] = g_idx[bc*CAP + i];
    __syncthreads();

    const float4* __restrict__ base4 = (const float4*)(enc + (size_t)b * Pp * Ee);
    float4 a0 = {0,0,0,0}, a1 = a0, a2 = a0, a3 = a0;

    int i = warp;
    // 8 loads in flight per warp (MLP=8) against 577-cyc DRAM latency
    for (; i + 28 < n; i += 32) {
        float4 v0 = __ldcs(&base4[(size_t)s_idx[i     ]*32 + lane]);
        float4 v1 = __ldcs(&base4[(size_t)s_idx[i +  4]*32 + lane]);
        float4 v2 = __ldcs(&base4[(size_t)s_idx[i +  8]*32 + lane]);
        float4 v3 = __ldcs(&base4[(size_t)s_idx[i + 12]*32 + lane]);
        float4 v4 = __ldcs(&base4[(size_t)s_idx[i + 16]*32 + lane]);
        float4 v5 = __ldcs(&base4[(size_t)s_idx[i + 20]*32 + lane]);
        float4 v6 = __ldcs(&base4[(size_t)s_idx[i + 24]*32 + lane]);
        float4 v7 = __ldcs(&base4[(size_t)s_idx[i + 28]*32 + lane]);
        f4add(a0, v0); f4add(a1, v1); f4add(a2, v2); f4add(a3, v3);
        f4add(a0, v4); f4add(a1, v5); f4add(a2, v6); f4add(a3, v7);
    }
    for (; i + 12 < n; i += 16) {
        float4 v0 = __ldcs(&base4[(size_t)s_idx[i     ]*32 + lane]);
        float4 v1 = __ldcs(&base4[(size_t)s_idx[i +  4]*32 + lane]);
        float4 v2 = __ldcs(&base4[(size_t)s_idx[i +  8]*32 + lane]);
        float4 v3 = __ldcs(&base4[(size_t)s_idx[i + 12]*32 + lane]);
        f4add(a0, v0); f4add(a1, v1); f4add(a2, v2); f4add(a3, v3);
    }
    for (; i < n; i += 4)
        f4add(a0, __ldcs(&base4[(size_t)s_idx[i]*32 + lane]));

    f4add(a0, a1); f4add(a2, a3); f4add(a0, a2);

    if (warp) s_red[warp-1][lane] = a0;
    __syncthreads();
    if (warp == 0) {
        f4add(a0, s_red[0][lane]);
        f4add(a0, s_red[1][lane]);
        f4add(a0, s_red[2][lane]);
        float inv = 1.f / (float)(n_full > 0 ? n_full : 1);
        a0.x *= inv; a0.y *= inv; a0.z *= inv; a0.w *= inv;
        ((float4*)s_mean)[lane] = a0;
    }
    __syncthreads();

    // ---- fused projection: out[t] = bias[t] + sum_k mean[k] * Wt[k][t] ----
    const float* __restrict__ wt = g_wt + t;     // column t, row-stride Ee
    float acc = __ldg(bias + t);
    #pragma unroll 8
    for (int k = 0; k < Ee; k++)
        acc = fmaf(s_mean[k], __ldg(wt + k*Ee), acc);
    ce[(size_t)bc*Ee + t] = acc;
}

// ---------------- K4: gather projected cluster embs back to nodes ----------------
#define PCH 625
#define GATHER_SMEM ((Cc*Ee + PCH + 3) * 4)
__global__ void __launch_bounds__(256) k_gather(const float* __restrict__ ce,
                                                float* __restrict__ gn) {
    extern __shared__ float s_dyn[];
    float* s_tab = s_dyn;                       // [Cc][Ee]
    int*   s_id  = (int*)(s_dyn + Cc*Ee);       // [PCH]

    int b  = blockIdx.y;
    int p0 = blockIdx.x * PCH;
    int cnt = Pp - p0; if (cnt > PCH) cnt = PCH;

    const float4* __restrict__ cb4 = (const float4*)(ce + (size_t)b * Cc * Ee);
    for (int j = threadIdx.x; j < Cc*Ee/4; j += 256)
        ((float4*)s_tab)[j] = cb4[j];
    const int* __restrict__ idb = g_ids + b*Pp + p0;
    for (int j = threadIdx.x; j < cnt; j += 256)
        s_id[j] = idb[j];
    __syncthreads();

    int lane = threadIdx.x & 31;
    int warp = threadIdx.x >> 5;
    float4* __restrict__ out = (float4*)(gn + ((size_t)b*Pp + p0)*Ee);

    int p = warp;
    for (; p + 8 < cnt; p += 16) {
        int c0 = s_id[p], c1 = s_id[p + 8];
        float4 v0 = ((const float4*)(s_tab + c0*Ee))[lane];
        float4 v1 = ((const float4*)(s_tab + c1*Ee))[lane];
        __stcs(&out[(size_t)p      *32 + lane], v0);
        __stcs(&out[(size_t)(p + 8)*32 + lane], v1);
    }
    for (; p < cnt; p += 8) {
        int c = s_id[p];
        float4 v = ((const float4*)(s_tab + c*Ee))[lane];
        __stcs(&out[(size_t)p*32 + lane], v);
    }
}

// ---------------- launch ----------------
extern "C" void kernel_launch(void* const* d_in, const int* in_sizes, int n_in,
                              void* d_out, int out_size) {
    const float* enc  = nullptr;
    const void*  ids  = nullptr;
    const float* W    = nullptr;
    const float* bias = nullptr;
    for (int i = 0; i < n_in; i++) {
        switch (in_sizes[i]) {
            case Bb*Pp*Ee: enc  = (const float*)d_in[i]; break;
            case Bb*Pp:    ids  = d_in[i];               break;
            case Ee*Ee:    W    = (const float*)d_in[i]; break;
            case Ee:       bias = (const float*)d_in[i]; break;
            default: break;
        }
    }

    float* ce = (float*)d_out;                       // [B, C, E]
    float* gn = (float*)d_out + (size_t)BC * Ee;     // [B, P, E]

    cudaFuncSetAttribute(k_gather, cudaFuncAttributeMaxDynamicSharedMemorySize, GATHER_SMEM);

    k_init  <<<(Ee*Ee + 255)/256, 256>>>((const int*)ids, W);
    k_bucket<<<(Bb*Pp + 255)/256, 256>>>(ids);
    k_mean  <<<BC, 128>>>(enc, bias, ce);
    k_gather<<<dim3((Pp + PCH - 1)/PCH, Bb), 256, GATHER_SMEM>>>(ce, gn);
}

// round 16
// speedup vs baseline: 1.0597x; 1.0277x over previous
#include <cuda_runtime.h>
#include <cstdio>

#define Bb 64
#define Pp 10000
#define Ee 128
#define Cc 100
#define CAP 384
#define BC (Bb*Cc)

// ---------------- scratch (no allocations allowed) ----------------
__device__ int   g_cnt[BC];
__device__ int   g_idx[BC*CAP];
__device__ float g_wt4[Ee*Ee];       // packed: g_wt4[(k/4)*Ee*4 + e*4 + (k%4)] = W[e][k]
__device__ int   g_ids[Bb*Pp];
__device__ int   g_is64;

__device__ __forceinline__ void f4add(float4& a, const float4 b) {
    a.x += b.x; a.y += b.y; a.z += b.z; a.w += b.w;
}

// ---------------- K0: zero counters + W repack + dtype detect ----------------
__global__ void k_init(const int* __restrict__ ids32, const float* __restrict__ W) {
    int i = blockIdx.x * blockDim.x + threadIdx.x;
    if (i < BC) g_cnt[i] = 0;
    if (i < Ee*Ee) {                      // one-time scattered repack (tiny)
        int e = i >> 7, k = i & 127;      // coalesced read of W row e
        g_wt4[(k >> 2)*Ee*4 + e*4 + (k & 3)] = W[i];
    }
    if (i == 0) {
        int all0 = 1;
        #pragma unroll 4
        for (int j = 0; j < 64; j++) {
            if (ids32[2*j + 1] != 0) { all0 = 0; break; }
        }
        g_is64 = all0;
    }
}

// ---------------- K1: bucket node indices by (batch, cluster) ----------------
__global__ void k_bucket(const void* __restrict__ ids_raw) {
    int i = blockIdx.x * blockDim.x + threadIdx.x;   // over B*P
    if (i >= Bb*Pp) return;
    int c;
    if (g_is64) c = (int)((const long long*)ids_raw)[i];
    else        c = ((const int*)ids_raw)[i];
    g_ids[i] = c;
    int b = i / Pp;
    int pos = atomicAdd(&g_cnt[b*Cc + c], 1);
    if (pos < CAP) g_idx[(b*Cc + c)*CAP + pos] = i - b*Pp;
}

// ---------------- K2: fused segment-mean + projection ----------------
// Mean phase: float4 rows, warp-per-row, MLP=8 (DRAM-bound).
// Proj tail v2: thread t computes out column t with FLOAT4 k-packing --
// w = g_wt4[kq*Ee + t] holds W[.][4kq..4kq+3] for column t; consecutive t are
// consecutive 16B so each kq step is ONE coalesced LDG.128 per warp (R15's
// scalar version cost 4x the LSU cycles and serialized ~49us chip-wide).
__global__ void __launch_bounds__(128) k_mean(const float* __restrict__ enc,
                                              const float* __restrict__ bias,
                                              float* __restrict__ ce) {
    int bc   = blockIdx.x;            // (b, c)
    int b    = bc / Cc;
    int warp = threadIdx.x >> 5;
    int lane = threadIdx.x & 31;
    int t    = threadIdx.x;

    __shared__ int    s_idx[CAP];
    __shared__ float4 s_red[3][32];
    __shared__ float  s_mean[Ee];

    int n_full = g_cnt[bc];
    int n = n_full < CAP ? n_full : CAP;
    for (int i = t; i < n; i += 128) s_idx[i] = g_idx[bc*CAP + i];
    __syncthreads();

    const float4* __restrict__ base4 = (const float4*)(enc + (size_t)b * Pp * Ee);
    float4 a0 = {0,0,0,0}, a1 = a0, a2 = a0, a3 = a0;

    int i = warp;
    // 8 loads in flight per warp (MLP=8) against 577-cyc DRAM latency
    for (; i + 28 < n; i += 32) {
        float4 v0 = __ldcs(&base4[(size_t)s_idx[i     ]*32 + lane]);
        float4 v1 = __ldcs(&base4[(size_t)s_idx[i +  4]*32 + lane]);
        float4 v2 = __ldcs(&base4[(size_t)s_idx[i +  8]*32 + lane]);
        float4 v3 = __ldcs(&base4[(size_t)s_idx[i + 12]*32 + lane]);
        float4 v4 = __ldcs(&base4[(size_t)s_idx[i + 16]*32 + lane]);
        float4 v5 = __ldcs(&base4[(size_t)s_idx[i + 20]*32 + lane]);
        float4 v6 = __ldcs(&base4[(size_t)s_idx[i + 24]*32 + lane]);
        float4 v7 = __ldcs(&base4[(size_t)s_idx[i + 28]*32 + lane]);
        f4add(a0, v0); f4add(a1, v1); f4add(a2, v2); f4add(a3, v3);
        f4add(a0, v4); f4add(a1, v5); f4add(a2, v6); f4add(a3, v7);
    }
    for (; i + 12 < n; i += 16) {
        float4 v0 = __ldcs(&base4[(size_t)s_idx[i     ]*32 + lane]);
        float4 v1 = __ldcs(&base4[(size_t)s_idx[i +  4]*32 + lane]);
        float4 v2 = __ldcs(&base4[(size_t)s_idx[i +  8]*32 + lane]);
        float4 v3 = __ldcs(&base4[(size_t)s_idx[i + 12]*32 + lane]);
        f4add(a0, v0); f4add(a1, v1); f4add(a2, v2); f4add(a3, v3);
    }
    for (; i < n; i += 4)
        f4add(a0, __ldcs(&base4[(size_t)s_idx[i]*32 + lane]));

    f4add(a0, a1); f4add(a2, a3); f4add(a0, a2);

    if (warp) s_red[warp-1][lane] = a0;
    __syncthreads();
    if (warp == 0) {
        f4add(a0, s_red[0][lane]);
        f4add(a0, s_red[1][lane]);
        f4add(a0, s_red[2][lane]);
        float inv = 1.f / (float)(n_full > 0 ? n_full : 1);
        a0.x *= inv; a0.y *= inv; a0.z *= inv; a0.w *= inv;
        ((float4*)s_mean)[lane] = a0;
    }
    __syncthreads();

    // ---- fused projection, float4 over k ----
    const float4* __restrict__ wt4 = (const float4*)g_wt4;   // [32][Ee] float4
    const float4* __restrict__ m4  = (const float4*)s_mean;  // [32]
    float acc = __ldg(bias + t);
    #pragma unroll 8
    for (int kq = 0; kq < 32; kq++) {
        float4 w = __ldg(&wt4[kq*Ee + t]);    // coalesced LDG.128, L1-hot
        float4 m = m4[kq];                     // LDS.128 broadcast
        acc = fmaf(m.x, w.x, acc);
        acc = fmaf(m.y, w.y, acc);
        acc = fmaf(m.z, w.z, acc);
        acc = fmaf(m.w, w.w, acc);
    }
    ce[(size_t)bc*Ee + t] = acc;
}

// ---------------- K4: gather projected cluster embs back to nodes ----------------
// v2: NO smem table -- ce rows are read via __ldg (51.2KB/batch stays L1-hot;
// reads are coalesced 512B rows). smem drops to 2.5KB so occupancy goes
// reg-limited (~6 blocks/SM = 48 warps, was 24): more stores in flight
// against the store-drain latency that had issue stuck at 9.2%.
#define PCH 625
#define GATHER_SMEM ((PCH + 4) * 4)
__global__ void __launch_bounds__(256) k_gather(const float* __restrict__ ce,
                                                float* __restrict__ gn) {
    extern __shared__ float s_dyn[];
    int* s_id = (int*)s_dyn;                    // [PCH]

    int b  = blockIdx.y;
    int p0 = blockIdx.x * PCH;
    int cnt = Pp - p0; if (cnt > PCH) cnt = PCH;

    const int* __restrict__ idb = g_ids + b*Pp + p0;
    for (int j = threadIdx.x; j < cnt; j += 256)
        s_id[j] = idb[j];
    __syncthreads();

    int lane = threadIdx.x & 31;
    int warp = threadIdx.x >> 5;
    const float4* __restrict__ tab = (const float4*)(ce + (size_t)b * Cc * Ee);
    float4* __restrict__ out = (float4*)(gn + ((size_t)b*Pp + p0)*Ee);

    int p = warp;
    for (; p + 8 < cnt; p += 16) {
        int c0 = s_id[p], c1 = s_id[p + 8];
        float4 v0 = __ldg(&tab[c0*32 + lane]);
        float4 v1 = __ldg(&tab[c1*32 + lane]);
        __stcs(&out[(size_t)p      *32 + lane], v0);
        __stcs(&out[(size_t)(p + 8)*32 + lane], v1);
    }
    for (; p < cnt; p += 8) {
        int c = s_id[p];
        float4 v = __ldg(&tab[c*32 + lane]);
        __stcs(&out[(size_t)p*32 + lane], v);
    }
}

// ---------------- launch ----------------
extern "C" void kernel_launch(void* const* d_in, const int* in_sizes, int n_in,
                              void* d_out, int out_size) {
    const float* enc  = nullptr;
    const void*  ids  = nullptr;
    const float* W    = nullptr;
    const float* bias = nullptr;
    for (int i = 0; i < n_in; i++) {
        switch (in_sizes[i]) {
            case Bb*Pp*Ee: enc  = (const float*)d_in[i]; break;
            case Bb*Pp:    ids  = d_in[i];               break;
            case Ee*Ee:    W    = (const float*)d_in[i]; break;
            case Ee:       bias = (const float*)d_in[i]; break;
            default: break;
        }
    }

    float* ce = (float*)d_out;                       // [B, C, E]
    float* gn = (float*)d_out + (size_t)BC * Ee;     // [B, P, E]

    cudaFuncSetAttribute(k_gather, cudaFuncAttributeMaxDynamicSharedMemorySize, GATHER_SMEM);

    k_init  <<<(Ee*Ee + 255)/256, 256>>>((const int*)ids, W);
    k_bucket<<<(Bb*Pp + 255)/256, 256>>>(ids);
    k_mean  <<<BC, 128>>>(enc, bias, ce);
    k_gather<<<dim3((Pp + PCH - 1)/PCH, Bb), 256, GATHER_SMEM>>>(ce, gn);
}